// round 1
// baseline (speedup 1.0000x reference)
#include <cuda_runtime.h>

// Net_58712202936903 — fused 2-layer multiplicative MLP, fp32, FFMA-bound.
// Outputs (concat): v_t[65536], v_y[65536], v_grad[65536], v_center[512].
// v_grad is computed as a forward-mode JVP (tangent = l1_dot), avoiding the
// reference's explicit (b,128,8) Jacobian.

#define H       128
#define NIN     8
#define WST     132   // padded stride for transposed layer-2 weights (float4-aligned, conflict-free)

// Shared memory layout (floats), identical total for both kernels:
//  sW1t  : H*WST      = 16896   (W1_2 transposed: [k][o])
//  sW2t  : H*WST      = 16896   (W2_2 transposed)
//  sW11t : NIN*H      = 1024    (W1_1 transposed: [j][h])
//  sW21t : NIN*H      = 1024
//  sb11  : H          = 128
//  sb21  : H          = 128
//  then fwd:  sY[128*H]=16384, sX[128*NIN]=1024
//  then jvp:  sY[64*H]=8192, sYd[64*H]=8192, sX[64*NIN]=512, sXd[64*NIN]=512
// total = 53504 floats = 214016 bytes (< 227 KB limit)
#define SMEM_FLOATS 53504
#define SMEM_BYTES  (SMEM_FLOATS * 4)

__device__ __forceinline__ float warp_sum(float v) {
    v += __shfl_xor_sync(0xffffffffu, v, 16);
    v += __shfl_xor_sync(0xffffffffu, v, 8);
    v += __shfl_xor_sync(0xffffffffu, v, 4);
    v += __shfl_xor_sync(0xffffffffu, v, 2);
    v += __shfl_xor_sync(0xffffffffu, v, 1);
    return v;
}

// Cooperative staging of all weights into shared memory (once per block).
__device__ __forceinline__ void stage_weights(
    float* sW1t, float* sW2t, float* sW11t, float* sW21t, float* sb11, float* sb21,
    const float* __restrict__ W12, const float* __restrict__ W22,
    const float* __restrict__ W11, const float* __restrict__ W21,
    const float* __restrict__ b11, const float* __restrict__ b21, int t)
{
    // layer-2 weights, transposed, padded stride: sWxt[k*WST + o] = W[o*H + k]
    for (int i = t; i < H * H; i += 256) {
        int k = i & (H - 1);
        int o = i >> 7;
        sW1t[k * WST + o] = W12[o * H + k];   // coalesced global read
        sW2t[k * WST + o] = W22[o * H + k];
    }
    // layer-1 weights, transposed: sW11t[j*H + h] = W11[h*NIN + j]
    for (int i = t; i < H * NIN; i += 256) {
        int h = i >> 3;
        int j = i & (NIN - 1);
        sW11t[j * H + h] = W11[i];
        sW21t[j * H + h] = W21[i];
    }
    if (t < H) { sb11[t] = b11[t]; sb21[t] = b21[t]; }
}

// ---------------------------------------------------------------------------
// Forward kernel: out[s] = w_out . ((W12 y + b12) * (W22 y + b22)),
//                 y = (W11 x + b11) * (W21 x + b21)
// Handles two concatenated sources (T and center) in one launch.
// TB = 128 samples/tile; thread (tx,ty): o in {4tx..4tx+3}, s in {16ty..16ty+15}
// ---------------------------------------------------------------------------
extern "C" __global__ void __launch_bounds__(256, 1)
fwd_kernel(const float* __restrict__ x1, int n1,
           const float* __restrict__ x2, int n2,
           float* __restrict__ out1, float* __restrict__ out2,
           const float* __restrict__ W11, const float* __restrict__ b11,
           const float* __restrict__ W21, const float* __restrict__ b21,
           const float* __restrict__ W12, const float* __restrict__ b12,
           const float* __restrict__ W22, const float* __restrict__ b22,
           const float* __restrict__ wout)
{
    extern __shared__ float smem[];
    const int TB = 128;
    float* sW1t  = smem;
    float* sW2t  = sW1t  + H * WST;
    float* sW11t = sW2t  + H * WST;
    float* sW21t = sW11t + NIN * H;
    float* sb11  = sW21t + NIN * H;
    float* sb21  = sb11  + H;
    float* sY    = sb21  + H;          // TB*H
    float* sX    = sY    + TB * H;     // TB*NIN

    const int t  = threadIdx.x;
    const int tx = t & 31;
    const int ty = t >> 5;

    stage_weights(sW1t, sW2t, sW11t, sW21t, sb11, sb21,
                  W12, W22, W11, W21, b11, b21, t);

    float rb1[4], rb2[4], wo[4];
#pragma unroll
    for (int oo = 0; oo < 4; oo++) {
        int o = 4 * tx + oo;
        rb1[oo] = b12[o];
        rb2[oo] = b22[o];
        wo[oo]  = wout[o];
    }

    const int nt1 = n1 / TB;
    const int nt2 = n2 / TB;

    for (int tile = blockIdx.x; tile < nt1 + nt2; tile += gridDim.x) {
        const float* xsrc;
        float* osrc;
        int base;
        if (tile < nt1) { xsrc = x1; osrc = out1; base = tile * TB; }
        else            { xsrc = x2; osrc = out2; base = (tile - nt1) * TB; }

        __syncthreads();  // previous tile's readers done (also covers staging on iter 0)
        for (int i = t; i < TB * NIN; i += 256) sX[i] = xsrc[base * NIN + i];
        __syncthreads();

        // layer 1
        for (int i = t; i < TB * H; i += 256) {
            int s = i >> 7;
            int h = i & (H - 1);
            float z1 = sb11[h], z2 = sb21[h];
            const float* xs = sX + s * NIN;
#pragma unroll
            for (int j = 0; j < NIN; j++) {
                z1 += sW11t[j * H + h] * xs[j];
                z2 += sW21t[j * H + h] * xs[j];
            }
            sY[i] = z1 * z2;
        }
        __syncthreads();

        // layer 2: register-tiled
        float a1[16][4], a2[16][4];
#pragma unroll
        for (int ss = 0; ss < 16; ss++)
#pragma unroll
            for (int oo = 0; oo < 4; oo++) { a1[ss][oo] = rb1[oo]; a2[ss][oo] = rb2[oo]; }

        const float* yrow = sY + ty * 16 * H;
        for (int k = 0; k < H; k += 4) {
            float w1r[4][4], w2r[4][4];
#pragma unroll
            for (int kk = 0; kk < 4; kk++) {
                float4 v1 = *(const float4*)(sW1t + (k + kk) * WST + 4 * tx);
                float4 v2 = *(const float4*)(sW2t + (k + kk) * WST + 4 * tx);
                w1r[kk][0] = v1.x; w1r[kk][1] = v1.y; w1r[kk][2] = v1.z; w1r[kk][3] = v1.w;
                w2r[kk][0] = v2.x; w2r[kk][1] = v2.y; w2r[kk][2] = v2.z; w2r[kk][3] = v2.w;
            }
#pragma unroll
            for (int ss = 0; ss < 16; ss++) {
                float4 yv = *(const float4*)(yrow + ss * H + k);
                float yk[4] = { yv.x, yv.y, yv.z, yv.w };
#pragma unroll
                for (int kk = 0; kk < 4; kk++)
#pragma unroll
                    for (int oo = 0; oo < 4; oo++) {
                        a1[ss][oo] += w1r[kk][oo] * yk[kk];
                        a2[ss][oo] += w2r[kk][oo] * yk[kk];
                    }
            }
        }

        // epilogue: weighted product + warp reduction over o
#pragma unroll
        for (int ss = 0; ss < 16; ss++) {
            float p = 0.f;
#pragma unroll
            for (int oo = 0; oo < 4; oo++) p += wo[oo] * a1[ss][oo] * a2[ss][oo];
            p = warp_sum(p);
            if (tx == 0) osrc[base + ty * 16 + ss] = p;
        }
    }
}

// ---------------------------------------------------------------------------
// JVP kernel: forward value v_y AND directional derivative v_grad in one pass.
// TB = 64 samples/tile; thread (tx,ty): o in {4tx..4tx+3}, s in {8ty..8ty+7}
// ---------------------------------------------------------------------------
extern "C" __global__ void __launch_bounds__(256, 1)
jvp_kernel(const float* __restrict__ x, const float* __restrict__ xd, int n,
           float* __restrict__ out_v, float* __restrict__ out_g,
           const float* __restrict__ W11, const float* __restrict__ b11,
           const float* __restrict__ W21, const float* __restrict__ b21,
           const float* __restrict__ W12, const float* __restrict__ b12,
           const float* __restrict__ W22, const float* __restrict__ b22,
           const float* __restrict__ wout)
{
    extern __shared__ float smem[];
    const int TB = 64;
    float* sW1t  = smem;
    float* sW2t  = sW1t  + H * WST;
    float* sW11t = sW2t  + H * WST;
    float* sW21t = sW11t + NIN * H;
    float* sb11  = sW21t + NIN * H;
    float* sb21  = sb11  + H;
    float* sY    = sb21  + H;          // TB*H
    float* sYd   = sY    + TB * H;     // TB*H
    float* sX    = sYd   + TB * H;     // TB*NIN
    float* sXd   = sX    + TB * NIN;   // TB*NIN

    const int t  = threadIdx.x;
    const int tx = t & 31;
    const int ty = t >> 5;

    stage_weights(sW1t, sW2t, sW11t, sW21t, sb11, sb21,
                  W12, W22, W11, W21, b11, b21, t);

    float rb1[4], rb2[4], wo[4];
#pragma unroll
    for (int oo = 0; oo < 4; oo++) {
        int o = 4 * tx + oo;
        rb1[oo] = b12[o];
        rb2[oo] = b22[o];
        wo[oo]  = wout[o];
    }

    const int ntiles = n / TB;
    for (int tile = blockIdx.x; tile < ntiles; tile += gridDim.x) {
        const int base = tile * TB;

        __syncthreads();
        for (int i = t; i < TB * NIN; i += 256) {
            sX[i]  = x [base * NIN + i];
            sXd[i] = xd[base * NIN + i];
        }
        __syncthreads();

        // layer 1 + tangent
        for (int i = t; i < TB * H; i += 256) {
            int s = i >> 7;
            int h = i & (H - 1);
            float z1 = sb11[h], z2 = sb21[h], d1 = 0.f, d2 = 0.f;
            const float* xs  = sX  + s * NIN;
            const float* xds = sXd + s * NIN;
#pragma unroll
            for (int j = 0; j < NIN; j++) {
                float w1 = sW11t[j * H + h];
                float w2 = sW21t[j * H + h];
                z1 += w1 * xs[j];
                z2 += w2 * xs[j];
                d1 += w1 * xds[j];
                d2 += w2 * xds[j];
            }
            sY[i]  = z1 * z2;
            sYd[i] = z1 * d2 + z2 * d1;
        }
        __syncthreads();

        // layer 2: value + tangent accumulators
        float a1[8][4], a2[8][4], g1[8][4], g2[8][4];
#pragma unroll
        for (int ss = 0; ss < 8; ss++)
#pragma unroll
            for (int oo = 0; oo < 4; oo++) {
                a1[ss][oo] = rb1[oo];
                a2[ss][oo] = rb2[oo];
                g1[ss][oo] = 0.f;
                g2[ss][oo] = 0.f;
            }

        const float* yrow  = sY  + ty * 8 * H;
        const float* ydrow = sYd + ty * 8 * H;
        for (int k = 0; k < H; k += 4) {
            float w1r[4][4], w2r[4][4];
#pragma unroll
            for (int kk = 0; kk < 4; kk++) {
                float4 v1 = *(const float4*)(sW1t + (k + kk) * WST + 4 * tx);
                float4 v2 = *(const float4*)(sW2t + (k + kk) * WST + 4 * tx);
                w1r[kk][0] = v1.x; w1r[kk][1] = v1.y; w1r[kk][2] = v1.z; w1r[kk][3] = v1.w;
                w2r[kk][0] = v2.x; w2r[kk][1] = v2.y; w2r[kk][2] = v2.z; w2r[kk][3] = v2.w;
            }
#pragma unroll
            for (int ss = 0; ss < 8; ss++) {
                float4 yv  = *(const float4*)(yrow  + ss * H + k);
                float4 ydv = *(const float4*)(ydrow + ss * H + k);
                float yk[4]  = { yv.x,  yv.y,  yv.z,  yv.w  };
                float ydk[4] = { ydv.x, ydv.y, ydv.z, ydv.w };
#pragma unroll
                for (int kk = 0; kk < 4; kk++)
#pragma unroll
                    for (int oo = 0; oo < 4; oo++) {
                        a1[ss][oo] += w1r[kk][oo] * yk[kk];
                        a2[ss][oo] += w2r[kk][oo] * yk[kk];
                        g1[ss][oo] += w1r[kk][oo] * ydk[kk];
                        g2[ss][oo] += w2r[kk][oo] * ydk[kk];
                    }
            }
        }

        // epilogue: v = sum_o wo*z1*z2 ; g = sum_o wo*(z1d*z2 + z1*z2d)
#pragma unroll
        for (int ss = 0; ss < 8; ss++) {
            float pv = 0.f, pg = 0.f;
#pragma unroll
            for (int oo = 0; oo < 4; oo++) {
                pv += wo[oo] * a1[ss][oo] * a2[ss][oo];
                pg += wo[oo] * (g1[ss][oo] * a2[ss][oo] + a1[ss][oo] * g2[ss][oo]);
            }
            pv = warp_sum(pv);
            pg = warp_sum(pg);
            if (tx == 0) {
                out_v[base + ty * 8 + ss] = pv;
                out_g[base + ty * 8 + ss] = pg;
            }
        }
    }
}

// ---------------------------------------------------------------------------
extern "C" void kernel_launch(void* const* d_in, const int* in_sizes, int n_in,
                              void* d_out, int out_size)
{
    const float* T      = (const float*)d_in[0];
    const float* l      = (const float*)d_in[1];
    const float* l1_dot = (const float*)d_in[2];
    const float* center = (const float*)d_in[3];
    const float* w11    = (const float*)d_in[4];
    const float* b11    = (const float*)d_in[5];
    const float* w21    = (const float*)d_in[6];
    const float* b21    = (const float*)d_in[7];
    const float* w12    = (const float*)d_in[8];
    const float* b12    = (const float*)d_in[9];
    const float* w22    = (const float*)d_in[10];
    const float* b22    = (const float*)d_in[11];
    const float* wout   = (const float*)d_in[12];

    float* out = (float*)d_out;
    const int NT = 65536;   // rows of T / l
    const int NC = 512;     // rows of center

    float* out_vt = out;                 // [NT]
    float* out_vy = out + NT;            // [NT]
    float* out_vg = out + 2 * NT;        // [NT]
    float* out_vc = out + 3 * NT;        // [NC]

    cudaFuncSetAttribute(fwd_kernel, cudaFuncAttributeMaxDynamicSharedMemorySize, SMEM_BYTES);
    cudaFuncSetAttribute(jvp_kernel, cudaFuncAttributeMaxDynamicSharedMemorySize, SMEM_BYTES);

    // T (512 tiles) + center (4 tiles) fused in one persistent launch
    fwd_kernel<<<148, 256, SMEM_BYTES>>>(T, NT, center, NC, out_vt, out_vc,
                                         w11, b11, w21, b21, w12, b12, w22, b22, wout);
    // l + tangent l1_dot -> v_y, v_grad (1024 tiles)
    jvp_kernel<<<148, 256, SMEM_BYTES>>>(l, l1_dot, NT, out_vy, out_vg,
                                         w11, b11, w21, b21, w12, b12, w22, b22, wout);
}